// round 15
// baseline (speedup 1.0000x reference)
#include <cuda_runtime.h>
#include <cuda_fp16.h>
#include <cstdint>

#define N_NODES 50000
#define N_EDGES 800000

// ---- scratch (__device__ globals; no alloc) ----
__device__ __half g_Wch[64 * 96];      // edge B: [n][k], k 0..63 = e_h block, 64..95 = ext block
__device__ __half g_ADh[128 * 64];     // node B: [n][k], n 0..63 = A cols(P), 64..127 = D cols(Q)
__device__ float  g_bias[64];          // b1@W2a + b2 (fp32)
__device__ float  g_PQ[(size_t)N_NODES * 128];  // per-node: P (0..63), Q (64..127)

__device__ __forceinline__ uint32_t f2h2(float lo, float hi) {
    uint32_t r;
    asm("cvt.rn.f16x2.f32 %0, %1, %2;" : "=r"(r) : "f"(hi), "f"(lo));
    return r;
}
__device__ __forceinline__ void stg_cs(float* p, float2 v) {
    asm volatile("st.global.cs.v2.f32 [%0], {%1,%2};" :: "l"(p), "f"(v.x), "f"(v.y));
}
__device__ __forceinline__ void prefetch_l1(const void* p) {
    asm volatile("prefetch.global.L1 [%0];" :: "l"(p));
}
__device__ __forceinline__ void mma_f16(float c[4], const uint32_t a[4], const uint32_t b[2]) {
    asm volatile(
        "mma.sync.aligned.m16n8k16.row.col.f32.f16.f16.f32 "
        "{%0,%1,%2,%3}, {%4,%5,%6,%7}, {%8,%9}, {%0,%1,%2,%3};"
        : "+f"(c[0]), "+f"(c[1]), "+f"(c[2]), "+f"(c[3])
        : "r"(a[0]), "r"(a[1]), "r"(a[2]), "r"(a[3]), "r"(b[0]), "r"(b[1]));
}
__device__ __forceinline__ void ldsm_x4(uint32_t& r0, uint32_t& r1, uint32_t& r2, uint32_t& r3,
                                        uint32_t addr) {
    asm volatile("ldmatrix.sync.aligned.m8n8.x4.shared.b16 {%0,%1,%2,%3}, [%4];"
                 : "=r"(r0), "=r"(r1), "=r"(r2), "=r"(r3) : "r"(addr));
}
__device__ __forceinline__ uint32_t smem_u32(const void* p) {
    return (uint32_t)__cvta_generic_to_shared(p);
}

// ---------------------------------------------------------------------------
// Kernel 1: fuse weights; emit fp16 [n][k] weight arrays + fp32 bias.
// ---------------------------------------------------------------------------
__global__ void __launch_bounds__(256) prep_kernel(
    const float* __restrict__ W1, const float* __restrict__ b1,
    const float* __restrict__ W2, const float* __restrict__ b2) {
    __shared__ float W2s[64 * 64];
    int t = threadIdx.x;
    for (int i = t; i < 64 * 64; i += 256) W2s[i] = W2[i];
    __syncthreads();

    int o = blockIdx.x * 256 + t;   // 12288 = 192*64 exactly
    {
        int i = o >> 6;
        int j = o & 63;
        float s0 = 0.f, s1 = 0.f, s2 = 0.f, s3 = 0.f;
#pragma unroll
        for (int k = 0; k < 64; k += 4) {
            float4 w = *(const float4*)(W1 + i * 64 + k);
            s0 = fmaf(w.x, W2s[(k + 0) * 64 + j], s0);
            s1 = fmaf(w.y, W2s[(k + 1) * 64 + j], s1);
            s2 = fmaf(w.z, W2s[(k + 2) * 64 + j], s2);
            s3 = fmaf(w.w, W2s[(k + 3) * 64 + j], s3);
        }
        __half hs = __float2half_rn((s0 + s1) + (s2 + s3));
        if (i < 64)       g_ADh[j * 64 + i] = hs;                  // A block: node B[n=j][k=i]
        else if (i < 128) g_Wch[j * 96 + (i - 64)] = hs;           // e_h block
        else              g_ADh[(64 + j) * 64 + (i - 128)] = hs;   // D block
    }
    if (blockIdx.x == 0) {
        for (int idx = t; idx < 32 * 64; idx += 256) {
            int kp = idx >> 6;
            int n = idx & 63;
            g_Wch[n * 96 + 64 + kp] = __float2half_rn(W2[(64 + kp) * 64 + n]);
        }
        if (t < 64) {
            float s0 = 0.f, s1 = 0.f;
#pragma unroll
            for (int k = 0; k < 64; k += 2) {
                s0 = fmaf(b1[k], W2s[k * 64 + t], s0);
                s1 = fmaf(b1[k + 1], W2s[(k + 1) * 64 + t], s1);
            }
            g_bias[t] = s0 + s1 + b2[t];
        }
    }
}

// ---------------------------------------------------------------------------
// Kernel 2: node projections PQ = h @ [A|D] via fp16 m16n8k16 mma (R13).
// ---------------------------------------------------------------------------
#define NA_W 36
#define NB_W 36
#define NSM_A_OFF 0
#define NSM_B_OFF (64 * NA_W)           // 2304 words
#define NSM_WORDS (NSM_B_OFF + 128 * NB_W)   // 6912 words = 27648 B

__global__ void __launch_bounds__(256) node_kernel(const float* __restrict__ h) {
    extern __shared__ uint32_t nsm[];
    uint32_t* As = nsm + NSM_A_OFF;
    uint32_t* Bs = nsm + NSM_B_OFF;

    int t = threadIdx.x;
    int wid = t >> 5;
    int lane = t & 31;
    int mw = wid >> 2;
    int nw = wid & 3;
    int lq = lane >> 2;
    int lr = lane & 3;

    int n0 = blockIdx.x * 64;

#pragma unroll
    for (int j = 0; j < 4; j++) {
        int i = t + j * 256;
        int r = i >> 3;
        int c4 = (i & 7) << 2;
        *(uint4*)(Bs + r * NB_W + c4) = *(const uint4*)((const uint32_t*)g_ADh + r * 32 + c4);
    }
#pragma unroll
    for (int j = 0; j < 4; j++) {
        int i = t + j * 256;
        int m = i >> 4;
        int c4 = (i & 15) << 2;
        int n = n0 + m;
        if (n >= N_NODES) n = N_NODES - 1;
        float4 v = *(const float4*)(h + (size_t)n * 64 + c4);
        uint2 w = make_uint2(f2h2(v.x, v.y), f2h2(v.z, v.w));
        *(uint2*)(As + m * NA_W + (c4 >> 1)) = w;
    }
    __syncthreads();

    float c[2][4][4];
#pragma unroll
    for (int mf = 0; mf < 2; mf++)
#pragma unroll
        for (int nf = 0; nf < 4; nf++)
#pragma unroll
            for (int i = 0; i < 4; i++) c[mf][nf][i] = 0.f;

#pragma unroll
    for (int ks = 0; ks < 4; ks++) {
        int kw = ks * 8;
        uint32_t a[2][4];
#pragma unroll
        for (int mf = 0; mf < 2; mf++) {
            const uint32_t* ap = As + (mw * 32 + mf * 16 + lq) * NA_W + kw + lr;
            a[mf][0] = ap[0];
            a[mf][1] = ap[8 * NA_W];
            a[mf][2] = ap[4];
            a[mf][3] = ap[8 * NA_W + 4];
        }
        uint32_t b[4][2];
#pragma unroll
        for (int nf = 0; nf < 4; nf++) {
            const uint32_t* bp = Bs + (nw * 32 + nf * 8 + lq) * NB_W + kw + lr;
            b[nf][0] = bp[0];
            b[nf][1] = bp[4];
        }
#pragma unroll
        for (int mf = 0; mf < 2; mf++)
#pragma unroll
            for (int nf = 0; nf < 4; nf++)
                mma_f16(c[mf][nf], a[mf], b[nf]);
    }

#pragma unroll
    for (int mf = 0; mf < 2; mf++)
#pragma unroll
        for (int half = 0; half < 2; half++) {
            int r = mw * 32 + mf * 16 + half * 8 + lq;
            int n = n0 + r;
            if (n < N_NODES) {
#pragma unroll
                for (int nf = 0; nf < 4; nf++) {
                    int col = nw * 32 + nf * 8 + 2 * lr;
                    float2 v = make_float2(c[mf][nf][half * 2 + 0], c[mf][nf][half * 2 + 1]);
                    *(float2*)(g_PQ + (size_t)n * 128 + col) = v;
                }
            }
        }
}

// ---------------------------------------------------------------------------
// Kernel 3: fp16 m16n8k16 edge GEMM + ldmatrix + L1 prefetch of PQ gathers.
// TILE_M=128, 2 CTAs/SM, streams evict-first.
// ---------------------------------------------------------------------------
#define TILE_M 128
#define NTILES (N_EDGES / TILE_M)       // 6250
#define EDGE_GRID 296                   // 148 SMs x 2 CTAs

#define EA_W 52
#define EB_W 52
#define SMEM_A_OFF 0
#define SMEM_B_OFF (TILE_M * EA_W)                 // 6656 words
#define SMEM_BIAS_OFF (SMEM_B_OFF + 64 * EB_W)     // 9984 words
#define SMEM_WORDS (SMEM_BIAS_OFF + 64)            // 10048 words = 40192 B

__global__ void __launch_bounds__(256, 2) edge_kernel(
    const float* __restrict__ e_h, const float* __restrict__ ext,
    const int* __restrict__ src, const int* __restrict__ dst,
    float* __restrict__ out)
{
    extern __shared__ uint32_t smw[];
    uint32_t* As = smw + SMEM_A_OFF;
    uint32_t* Bs = smw + SMEM_B_OFF;
    float*  bias = (float*)(smw + SMEM_BIAS_OFF);

    int t = threadIdx.x;
    int wid = t >> 5;
    int lane = t & 31;
    int mw = wid >> 1;        // 0..3 -> M rows [mw*32, +32)
    int nw = wid & 1;         // 0..1 -> N cols [nw*32, +32)
    int lq = lane >> 2;       // 0..7
    int lr = lane & 3;        // 0..3

    // stage B = g_Wch raw copy: 64 rows x 12 uint4 -> stride 52 words
#pragma unroll
    for (int j = 0; j < 4; j++) {
        int i = t + j * 256;
        int r = i >> 4;
        int s = i & 15;
        if (s < 12)
            *(uint4*)(Bs + r * EB_W + s * 4) =
                *(const uint4*)((const uint32_t*)g_Wch + r * 48 + s * 4);
    }
    if (t < 64) bias[t] = g_bias[t];

    // ldmatrix lane base addresses (bytes)
    int g8 = lane >> 3;
    int l8 = lane & 7;
    uint32_t aAddr = smem_u32(As) +
        (((mw * 32 + ((g8 & 1) ? 8 : 0) + l8) * EA_W) + ((g8 >> 1) * 4)) * 4;
    uint32_t bAddr = smem_u32(Bs) +
        (((nw * 32 + ((g8 >> 1) ? 8 : 0) + l8) * EB_W) + ((g8 & 1) * 4)) * 4;

    for (int tile = blockIdx.x; tile < NTILES; tile += EDGE_GRID) {
        int e0 = tile * TILE_M;
        __syncthreads();   // prev-iter LDS of As done (first iter: B/bias visible)

        // ---- stage A: e_h -> k 0..63 (words 0..31), streaming, cvt fp16 ----
#pragma unroll
        for (int i = t; i < 2048; i += 256) {
            int m = i >> 4;
            int c4 = (i & 15) << 2;
            float4 v = __ldcs((const float4*)(e_h + (size_t)(e0 + m) * 64 + c4));
            uint2 w = make_uint2(f2h2(v.x, v.y), f2h2(v.z, v.w));
            *(uint2*)(As + m * EA_W + (c4 >> 1)) = w;
        }
        // ---- stage A: ext -> k 64..95 (words 32..47) ----
#pragma unroll
        for (int i = t; i < 1024; i += 256) {
            int m = i >> 3;
            int c4 = (i & 7) << 2;
            float4 v = __ldcs((const float4*)(ext + (size_t)(e0 + m) * 32 + c4));
            uint2 w = make_uint2(f2h2(v.x, v.y), f2h2(v.z, v.w));
            *(uint2*)(As + m * EA_W + 32 + (c4 >> 1)) = w;
        }

        // ---- prefetch gather indices + L1-prefetch the PQ lines ----
        int sv[2][2], dv[2][2];
#pragma unroll
        for (int mf = 0; mf < 2; mf++)
#pragma unroll
            for (int half = 0; half < 2; half++) {
                int e = e0 + mw * 32 + mf * 16 + half * 8 + lq;
                sv[mf][half] = src[e];
                dv[mf][half] = dst[e];
            }
#pragma unroll
        for (int mf = 0; mf < 2; mf++)
#pragma unroll
            for (int half = 0; half < 2; half++) {
                // this thread's P slice: cols nw*32..+31 -> one aligned 128B line
                prefetch_l1(g_PQ + (size_t)sv[mf][half] * 128 + nw * 32);
                prefetch_l1(g_PQ + (size_t)dv[mf][half] * 128 + 64 + nw * 32);
            }
        __syncthreads();

        // ---- mma mainloop: 6 K-steps of 16, ldmatrix frag loads ----
        float c[2][4][4];
#pragma unroll
        for (int mf = 0; mf < 2; mf++)
#pragma unroll
            for (int nf = 0; nf < 4; nf++)
#pragma unroll
                for (int i = 0; i < 4; i++) c[mf][nf][i] = 0.f;

#pragma unroll
        for (int ks = 0; ks < 6; ks++) {
            uint32_t kofs = ks * 32;
            uint32_t a[2][4];
            ldsm_x4(a[0][0], a[0][1], a[0][2], a[0][3], aAddr + kofs);
            ldsm_x4(a[1][0], a[1][1], a[1][2], a[1][3], aAddr + 16 * EA_W * 4 + kofs);
            uint32_t b[4][2];
            ldsm_x4(b[0][0], b[0][1], b[1][0], b[1][1], bAddr + kofs);
            ldsm_x4(b[2][0], b[2][1], b[3][0], b[3][1], bAddr + 16 * EB_W * 4 + kofs);
#pragma unroll
            for (int mf = 0; mf < 2; mf++)
#pragma unroll
                for (int nf = 0; nf < 4; nf++)
                    mma_f16(c[mf][nf], a[mf], b[nf]);
        }

        // ---- epilogue: +P[src] +Q[dst] +bias, ReLU, streaming store ----
#pragma unroll
        for (int mf = 0; mf < 2; mf++) {
#pragma unroll
            for (int half = 0; half < 2; half++) {
                int r = mw * 32 + mf * 16 + half * 8 + lq;
                int e = e0 + r;
                const float* P = g_PQ + (size_t)sv[mf][half] * 128;
                const float* Q = g_PQ + (size_t)dv[mf][half] * 128 + 64;
#pragma unroll
                for (int nf = 0; nf < 4; nf++) {
                    int col = nw * 32 + nf * 8 + 2 * lr;
                    float2 p = __ldg((const float2*)(P + col));
                    float2 q = __ldg((const float2*)(Q + col));
                    float2 bvv = *(const float2*)(bias + col);
                    float cx = c[mf][nf][half * 2 + 0];
                    float cy = c[mf][nf][half * 2 + 1];
                    float2 rv;
                    rv.x = fmaxf(cx + p.x + q.x + bvv.x, 0.f);
                    rv.y = fmaxf(cy + p.y + q.y + bvv.y, 0.f);
                    stg_cs(out + (size_t)e * 64 + col, rv);
                }
            }
        }
    }
}

// ---------------------------------------------------------------------------
extern "C" void kernel_launch(void* const* d_in, const int* in_sizes, int n_in,
                              void* d_out, int out_size) {
    const float* h   = (const float*)d_in[0];
    const float* e_h = (const float*)d_in[1];
    const float* ext = (const float*)d_in[2];
    const float* W1  = (const float*)d_in[3];
    const float* b1  = (const float*)d_in[4];
    const float* W2  = (const float*)d_in[5];
    const float* b2  = (const float*)d_in[6];
    const int*   src = (const int*)d_in[7];
    const int*   dst = (const int*)d_in[8];
    float* out = (float*)d_out;

    static bool attr_set = false;
    if (!attr_set) {
        cudaFuncSetAttribute(edge_kernel, cudaFuncAttributeMaxDynamicSharedMemorySize,
                             SMEM_WORDS * 4);
        cudaFuncSetAttribute(node_kernel, cudaFuncAttributeMaxDynamicSharedMemorySize,
                             NSM_WORDS * 4);
        attr_set = true;
    }

    prep_kernel<<<48, 256>>>(W1, b1, W2, b2);
    node_kernel<<<(N_NODES + 63) / 64, 256, NSM_WORDS * 4>>>(h);
    edge_kernel<<<EDGE_GRID, 256, SMEM_WORDS * 4>>>(e_h, ext, src, dst, out);
}

// round 16
// speedup vs baseline: 1.0167x; 1.0167x over previous
#include <cuda_runtime.h>
#include <cuda_fp16.h>
#include <cstdint>

#define N_NODES 50000
#define N_EDGES 800000

// ---- scratch (__device__ globals; no alloc) ----
__device__ __half g_Wch[64 * 96];      // edge B: [n][k], k 0..63 = e_h block, 64..95 = ext block
__device__ __half g_ADh[128 * 64];     // node B: [n][k], n 0..63 = A cols(P), 64..127 = D cols(Q)
__device__ float  g_bias[64];          // b1@W2a + b2 (fp32)
__device__ float  g_PQ[(size_t)N_NODES * 128];  // per-node: P (0..63), Q (64..127)

__device__ __forceinline__ uint32_t f2h2(float lo, float hi) {
    uint32_t r;
    asm("cvt.rn.f16x2.f32 %0, %1, %2;" : "=r"(r) : "f"(hi), "f"(lo));
    return r;
}
__device__ __forceinline__ void stg_cs(float* p, float2 v) {
    asm volatile("st.global.cs.v2.f32 [%0], {%1,%2};" :: "l"(p), "f"(v.x), "f"(v.y));
}
__device__ __forceinline__ void mma_f16(float c[4], const uint32_t a[4], const uint32_t b[2]) {
    asm volatile(
        "mma.sync.aligned.m16n8k16.row.col.f32.f16.f16.f32 "
        "{%0,%1,%2,%3}, {%4,%5,%6,%7}, {%8,%9}, {%0,%1,%2,%3};"
        : "+f"(c[0]), "+f"(c[1]), "+f"(c[2]), "+f"(c[3])
        : "r"(a[0]), "r"(a[1]), "r"(a[2]), "r"(a[3]), "r"(b[0]), "r"(b[1]));
}
__device__ __forceinline__ void ldsm_x4(uint32_t& r0, uint32_t& r1, uint32_t& r2, uint32_t& r3,
                                        uint32_t addr) {
    asm volatile("ldmatrix.sync.aligned.m8n8.x4.shared.b16 {%0,%1,%2,%3}, [%4];"
                 : "=r"(r0), "=r"(r1), "=r"(r2), "=r"(r3) : "r"(addr));
}
__device__ __forceinline__ uint32_t smem_u32(const void* p) {
    return (uint32_t)__cvta_generic_to_shared(p);
}

// ---------------------------------------------------------------------------
// Kernel 1: fuse weights; emit fp16 [n][k] weight arrays + fp32 bias.
// ---------------------------------------------------------------------------
__global__ void __launch_bounds__(256) prep_kernel(
    const float* __restrict__ W1, const float* __restrict__ b1,
    const float* __restrict__ W2, const float* __restrict__ b2) {
    __shared__ float W2s[64 * 64];
    int t = threadIdx.x;
    for (int i = t; i < 64 * 64; i += 256) W2s[i] = W2[i];
    __syncthreads();

    int o = blockIdx.x * 256 + t;   // 12288 = 192*64 exactly
    {
        int i = o >> 6;
        int j = o & 63;
        float s0 = 0.f, s1 = 0.f, s2 = 0.f, s3 = 0.f;
#pragma unroll
        for (int k = 0; k < 64; k += 4) {
            float4 w = *(const float4*)(W1 + i * 64 + k);
            s0 = fmaf(w.x, W2s[(k + 0) * 64 + j], s0);
            s1 = fmaf(w.y, W2s[(k + 1) * 64 + j], s1);
            s2 = fmaf(w.z, W2s[(k + 2) * 64 + j], s2);
            s3 = fmaf(w.w, W2s[(k + 3) * 64 + j], s3);
        }
        __half hs = __float2half_rn((s0 + s1) + (s2 + s3));
        if (i < 64)       g_ADh[j * 64 + i] = hs;                  // A block: node B[n=j][k=i]
        else if (i < 128) g_Wch[j * 96 + (i - 64)] = hs;           // e_h block
        else              g_ADh[(64 + j) * 64 + (i - 128)] = hs;   // D block
    }
    if (blockIdx.x == 0) {
        for (int idx = t; idx < 32 * 64; idx += 256) {
            int kp = idx >> 6;
            int n = idx & 63;
            g_Wch[n * 96 + 64 + kp] = __float2half_rn(W2[(64 + kp) * 64 + n]);
        }
        if (t < 64) {
            float s0 = 0.f, s1 = 0.f;
#pragma unroll
            for (int k = 0; k < 64; k += 2) {
                s0 = fmaf(b1[k], W2s[k * 64 + t], s0);
                s1 = fmaf(b1[k + 1], W2s[(k + 1) * 64 + t], s1);
            }
            g_bias[t] = s0 + s1 + b2[t];
        }
    }
}

// ---------------------------------------------------------------------------
// Kernel 2: node projections PQ = h @ [A|D] via fp16 m16n8k16 mma (R13).
// ---------------------------------------------------------------------------
#define NA_W 36
#define NB_W 36
#define NSM_A_OFF 0
#define NSM_B_OFF (64 * NA_W)           // 2304 words
#define NSM_WORDS (NSM_B_OFF + 128 * NB_W)   // 6912 words = 27648 B

__global__ void __launch_bounds__(256) node_kernel(const float* __restrict__ h) {
    extern __shared__ uint32_t nsm[];
    uint32_t* As = nsm + NSM_A_OFF;
    uint32_t* Bs = nsm + NSM_B_OFF;

    int t = threadIdx.x;
    int wid = t >> 5;
    int lane = t & 31;
    int mw = wid >> 2;
    int nw = wid & 3;
    int lq = lane >> 2;
    int lr = lane & 3;

    int n0 = blockIdx.x * 64;

#pragma unroll
    for (int j = 0; j < 4; j++) {
        int i = t + j * 256;
        int r = i >> 3;
        int c4 = (i & 7) << 2;
        *(uint4*)(Bs + r * NB_W + c4) = *(const uint4*)((const uint32_t*)g_ADh + r * 32 + c4);
    }
#pragma unroll
    for (int j = 0; j < 4; j++) {
        int i = t + j * 256;
        int m = i >> 4;
        int c4 = (i & 15) << 2;
        int n = n0 + m;
        if (n >= N_NODES) n = N_NODES - 1;
        float4 v = *(const float4*)(h + (size_t)n * 64 + c4);
        uint2 w = make_uint2(f2h2(v.x, v.y), f2h2(v.z, v.w));
        *(uint2*)(As + m * NA_W + (c4 >> 1)) = w;
    }
    __syncthreads();

    float c[2][4][4];
#pragma unroll
    for (int mf = 0; mf < 2; mf++)
#pragma unroll
        for (int nf = 0; nf < 4; nf++)
#pragma unroll
            for (int i = 0; i < 4; i++) c[mf][nf][i] = 0.f;

#pragma unroll
    for (int ks = 0; ks < 4; ks++) {
        int kw = ks * 8;
        uint32_t a[2][4];
#pragma unroll
        for (int mf = 0; mf < 2; mf++) {
            const uint32_t* ap = As + (mw * 32 + mf * 16 + lq) * NA_W + kw + lr;
            a[mf][0] = ap[0];
            a[mf][1] = ap[8 * NA_W];
            a[mf][2] = ap[4];
            a[mf][3] = ap[8 * NA_W + 4];
        }
        uint32_t b[4][2];
#pragma unroll
        for (int nf = 0; nf < 4; nf++) {
            const uint32_t* bp = Bs + (nw * 32 + nf * 8 + lq) * NB_W + kw + lr;
            b[nf][0] = bp[0];
            b[nf][1] = bp[4];
        }
#pragma unroll
        for (int mf = 0; mf < 2; mf++)
#pragma unroll
            for (int nf = 0; nf < 4; nf++)
                mma_f16(c[mf][nf], a[mf], b[nf]);
    }

#pragma unroll
    for (int mf = 0; mf < 2; mf++)
#pragma unroll
        for (int half = 0; half < 2; half++) {
            int r = mw * 32 + mf * 16 + half * 8 + lq;
            int n = n0 + r;
            if (n < N_NODES) {
#pragma unroll
                for (int nf = 0; nf < 4; nf++) {
                    int col = nw * 32 + nf * 8 + 2 * lr;
                    float2 v = make_float2(c[mf][nf][half * 2 + 0], c[mf][nf][half * 2 + 1]);
                    *(float2*)(g_PQ + (size_t)n * 128 + col) = v;
                }
            }
        }
}

// ---------------------------------------------------------------------------
// Kernel 3: fp16 m16n8k16 edge GEMM + ldmatrix (R14 body), 3 CTAs/SM.
// TILE_M=128, streams evict-first, indices prefetched pre-mainloop.
// ---------------------------------------------------------------------------
#define TILE_M 128
#define NTILES (N_EDGES / TILE_M)       // 6250
#define EDGE_GRID 444                   // 148 SMs x 3 CTAs

#define EA_W 52
#define EB_W 52
#define SMEM_A_OFF 0
#define SMEM_B_OFF (TILE_M * EA_W)                 // 6656 words
#define SMEM_BIAS_OFF (SMEM_B_OFF + 64 * EB_W)     // 9984 words
#define SMEM_WORDS (SMEM_BIAS_OFF + 64)            // 10048 words = 40192 B

__global__ void __launch_bounds__(256, 3) edge_kernel(
    const float* __restrict__ e_h, const float* __restrict__ ext,
    const int* __restrict__ src, const int* __restrict__ dst,
    float* __restrict__ out)
{
    extern __shared__ uint32_t smw[];
    uint32_t* As = smw + SMEM_A_OFF;
    uint32_t* Bs = smw + SMEM_B_OFF;
    float*  bias = (float*)(smw + SMEM_BIAS_OFF);

    int t = threadIdx.x;
    int wid = t >> 5;
    int lane = t & 31;
    int mw = wid >> 1;        // 0..3 -> M rows [mw*32, +32)
    int nw = wid & 1;         // 0..1 -> N cols [nw*32, +32)
    int lq = lane >> 2;       // 0..7
    int lr = lane & 3;        // 0..3

    // stage B = g_Wch raw copy: 64 rows x 12 uint4 -> stride 52 words
#pragma unroll
    for (int j = 0; j < 4; j++) {
        int i = t + j * 256;
        int r = i >> 4;
        int s = i & 15;
        if (s < 12)
            *(uint4*)(Bs + r * EB_W + s * 4) =
                *(const uint4*)((const uint32_t*)g_Wch + r * 48 + s * 4);
    }
    if (t < 64) bias[t] = g_bias[t];

    // ldmatrix lane base addresses (bytes)
    int g8 = lane >> 3;
    int l8 = lane & 7;
    uint32_t aAddr = smem_u32(As) +
        (((mw * 32 + ((g8 & 1) ? 8 : 0) + l8) * EA_W) + ((g8 >> 1) * 4)) * 4;
    uint32_t bAddr = smem_u32(Bs) +
        (((nw * 32 + ((g8 >> 1) ? 8 : 0) + l8) * EB_W) + ((g8 & 1) * 4)) * 4;

    for (int tile = blockIdx.x; tile < NTILES; tile += EDGE_GRID) {
        int e0 = tile * TILE_M;
        __syncthreads();   // prev-iter LDS of As done (first iter: B/bias visible)

        // ---- stage A: e_h -> k 0..63 (words 0..31), streaming, cvt fp16 ----
#pragma unroll
        for (int i = t; i < 2048; i += 256) {
            int m = i >> 4;
            int c4 = (i & 15) << 2;
            float4 v = __ldcs((const float4*)(e_h + (size_t)(e0 + m) * 64 + c4));
            uint2 w = make_uint2(f2h2(v.x, v.y), f2h2(v.z, v.w));
            *(uint2*)(As + m * EA_W + (c4 >> 1)) = w;
        }
        // ---- stage A: ext -> k 64..95 (words 32..47) ----
#pragma unroll
        for (int i = t; i < 1024; i += 256) {
            int m = i >> 3;
            int c4 = (i & 7) << 2;
            float4 v = __ldcs((const float4*)(ext + (size_t)(e0 + m) * 32 + c4));
            uint2 w = make_uint2(f2h2(v.x, v.y), f2h2(v.z, v.w));
            *(uint2*)(As + m * EA_W + 32 + (c4 >> 1)) = w;
        }

        // ---- prefetch gather indices for this thread's 4 edge rows ----
        int sv[2][2], dv[2][2];
#pragma unroll
        for (int mf = 0; mf < 2; mf++)
#pragma unroll
            for (int half = 0; half < 2; half++) {
                int e = e0 + mw * 32 + mf * 16 + half * 8 + lq;
                sv[mf][half] = src[e];
                dv[mf][half] = dst[e];
            }
        __syncthreads();

        // ---- mma mainloop: 6 K-steps of 16, ldmatrix frag loads ----
        float c[2][4][4];
#pragma unroll
        for (int mf = 0; mf < 2; mf++)
#pragma unroll
            for (int nf = 0; nf < 4; nf++)
#pragma unroll
                for (int i = 0; i < 4; i++) c[mf][nf][i] = 0.f;

#pragma unroll
        for (int ks = 0; ks < 6; ks++) {
            uint32_t kofs = ks * 32;
            uint32_t a[2][4];
            ldsm_x4(a[0][0], a[0][1], a[0][2], a[0][3], aAddr + kofs);
            ldsm_x4(a[1][0], a[1][1], a[1][2], a[1][3], aAddr + 16 * EA_W * 4 + kofs);
            uint32_t b[4][2];
            ldsm_x4(b[0][0], b[0][1], b[1][0], b[1][1], bAddr + kofs);
            ldsm_x4(b[2][0], b[2][1], b[3][0], b[3][1], bAddr + 16 * EB_W * 4 + kofs);
#pragma unroll
            for (int mf = 0; mf < 2; mf++)
#pragma unroll
                for (int nf = 0; nf < 4; nf++)
                    mma_f16(c[mf][nf], a[mf], b[nf]);
        }

        // ---- epilogue: +P[src] +Q[dst] +bias, ReLU, streaming store ----
#pragma unroll
        for (int mf = 0; mf < 2; mf++) {
#pragma unroll
            for (int half = 0; half < 2; half++) {
                int r = mw * 32 + mf * 16 + half * 8 + lq;
                int e = e0 + r;
                const float* P = g_PQ + (size_t)sv[mf][half] * 128;
                const float* Q = g_PQ + (size_t)dv[mf][half] * 128 + 64;
#pragma unroll
                for (int nf = 0; nf < 4; nf++) {
                    int col = nw * 32 + nf * 8 + 2 * lr;
                    float2 p = __ldg((const float2*)(P + col));
                    float2 q = __ldg((const float2*)(Q + col));
                    float2 bvv = *(const float2*)(bias + col);
                    float cx = c[mf][nf][half * 2 + 0];
                    float cy = c[mf][nf][half * 2 + 1];
                    float2 rv;
                    rv.x = fmaxf(cx + p.x + q.x + bvv.x, 0.f);
                    rv.y = fmaxf(cy + p.y + q.y + bvv.y, 0.f);
                    stg_cs(out + (size_t)e * 64 + col, rv);
                }
            }
        }
    }
}

// ---------------------------------------------------------------------------
extern "C" void kernel_launch(void* const* d_in, const int* in_sizes, int n_in,
                              void* d_out, int out_size) {
    const float* h   = (const float*)d_in[0];
    const float* e_h = (const float*)d_in[1];
    const float* ext = (const float*)d_in[2];
    const float* W1  = (const float*)d_in[3];
    const float* b1  = (const float*)d_in[4];
    const float* W2  = (const float*)d_in[5];
    const float* b2  = (const float*)d_in[6];
    const int*   src = (const int*)d_in[7];
    const int*   dst = (const int*)d_in[8];
    float* out = (float*)d_out;

    static bool attr_set = false;
    if (!attr_set) {
        cudaFuncSetAttribute(edge_kernel, cudaFuncAttributeMaxDynamicSharedMemorySize,
                             SMEM_WORDS * 4);
        cudaFuncSetAttribute(node_kernel, cudaFuncAttributeMaxDynamicSharedMemorySize,
                             NSM_WORDS * 4);
        attr_set = true;
    }

    prep_kernel<<<48, 256>>>(W1, b1, W2, b2);
    node_kernel<<<(N_NODES + 63) / 64, 256, NSM_WORDS * 4>>>(h);
    edge_kernel<<<EDGE_GRID, 256, SMEM_WORDS * 4>>>(e_h, ext, src, dst, out);
}

// round 17
// speedup vs baseline: 1.0993x; 1.0813x over previous
#include <cuda_runtime.h>
#include <cuda_fp16.h>
#include <cstdint>

#define N_NODES 50000
#define N_EDGES 800000

// ---- scratch (__device__ globals; no alloc) ----
__device__ __half g_Wch[64 * 96];      // edge B: [n][k], k 0..63 = e_h block, 64..95 = ext block
__device__ __half g_ADh[128 * 64];     // node B: [n][k], n 0..63 = A cols(P), 64..127 = D cols(Q)
__device__ float  g_bias[64];          // b1@W2a + b2 (fp32)
__device__ __half g_PQh[(size_t)N_NODES * 128];  // per-node fp16: P (0..63), Q (64..127)

__device__ __forceinline__ uint32_t f2h2(float lo, float hi) {
    uint32_t r;
    asm("cvt.rn.f16x2.f32 %0, %1, %2;" : "=r"(r) : "f"(hi), "f"(lo));
    return r;
}
__device__ __forceinline__ void stg_cs(float* p, float2 v) {
    asm volatile("st.global.cs.v2.f32 [%0], {%1,%2};" :: "l"(p), "f"(v.x), "f"(v.y));
}
__device__ __forceinline__ void mma_f16(float c[4], const uint32_t a[4], const uint32_t b[2]) {
    asm volatile(
        "mma.sync.aligned.m16n8k16.row.col.f32.f16.f16.f32 "
        "{%0,%1,%2,%3}, {%4,%5,%6,%7}, {%8,%9}, {%0,%1,%2,%3};"
        : "+f"(c[0]), "+f"(c[1]), "+f"(c[2]), "+f"(c[3])
        : "r"(a[0]), "r"(a[1]), "r"(a[2]), "r"(a[3]), "r"(b[0]), "r"(b[1]));
}
__device__ __forceinline__ void ldsm_x4(uint32_t& r0, uint32_t& r1, uint32_t& r2, uint32_t& r3,
                                        uint32_t addr) {
    asm volatile("ldmatrix.sync.aligned.m8n8.x4.shared.b16 {%0,%1,%2,%3}, [%4];"
                 : "=r"(r0), "=r"(r1), "=r"(r2), "=r"(r3) : "r"(addr));
}
__device__ __forceinline__ uint32_t smem_u32(const void* p) {
    return (uint32_t)__cvta_generic_to_shared(p);
}

// ---------------------------------------------------------------------------
// Kernel 1: fuse weights; emit fp16 [n][k] weight arrays + fp32 bias.
// ---------------------------------------------------------------------------
__global__ void __launch_bounds__(256) prep_kernel(
    const float* __restrict__ W1, const float* __restrict__ b1,
    const float* __restrict__ W2, const float* __restrict__ b2) {
    __shared__ float W2s[64 * 64];
    int t = threadIdx.x;
    for (int i = t; i < 64 * 64; i += 256) W2s[i] = W2[i];
    __syncthreads();

    int o = blockIdx.x * 256 + t;   // 12288 = 192*64 exactly
    {
        int i = o >> 6;
        int j = o & 63;
        float s0 = 0.f, s1 = 0.f, s2 = 0.f, s3 = 0.f;
#pragma unroll
        for (int k = 0; k < 64; k += 4) {
            float4 w = *(const float4*)(W1 + i * 64 + k);
            s0 = fmaf(w.x, W2s[(k + 0) * 64 + j], s0);
            s1 = fmaf(w.y, W2s[(k + 1) * 64 + j], s1);
            s2 = fmaf(w.z, W2s[(k + 2) * 64 + j], s2);
            s3 = fmaf(w.w, W2s[(k + 3) * 64 + j], s3);
        }
        __half hs = __float2half_rn((s0 + s1) + (s2 + s3));
        if (i < 64)       g_ADh[j * 64 + i] = hs;                  // A block: node B[n=j][k=i]
        else if (i < 128) g_Wch[j * 96 + (i - 64)] = hs;           // e_h block
        else              g_ADh[(64 + j) * 64 + (i - 128)] = hs;   // D block
    }
    if (blockIdx.x == 0) {
        for (int idx = t; idx < 32 * 64; idx += 256) {
            int kp = idx >> 6;
            int n = idx & 63;
            g_Wch[n * 96 + 64 + kp] = __float2half_rn(W2[(64 + kp) * 64 + n]);
        }
        if (t < 64) {
            float s0 = 0.f, s1 = 0.f;
#pragma unroll
            for (int k = 0; k < 64; k += 2) {
                s0 = fmaf(b1[k], W2s[k * 64 + t], s0);
                s1 = fmaf(b1[k + 1], W2s[(k + 1) * 64 + t], s1);
            }
            g_bias[t] = s0 + s1 + b2[t];
        }
    }
}

// ---------------------------------------------------------------------------
// Kernel 2: node projections PQ = h @ [A|D] via fp16 m16n8k16 mma; fp16 output.
// ---------------------------------------------------------------------------
#define NA_W 36
#define NB_W 36
#define NSM_A_OFF 0
#define NSM_B_OFF (64 * NA_W)           // 2304 words
#define NSM_WORDS (NSM_B_OFF + 128 * NB_W)   // 6912 words = 27648 B

__global__ void __launch_bounds__(256) node_kernel(const float* __restrict__ h) {
    extern __shared__ uint32_t nsm[];
    uint32_t* As = nsm + NSM_A_OFF;
    uint32_t* Bs = nsm + NSM_B_OFF;

    int t = threadIdx.x;
    int wid = t >> 5;
    int lane = t & 31;
    int mw = wid >> 2;
    int nw = wid & 3;
    int lq = lane >> 2;
    int lr = lane & 3;

    int n0 = blockIdx.x * 64;

#pragma unroll
    for (int j = 0; j < 4; j++) {
        int i = t + j * 256;
        int r = i >> 3;
        int c4 = (i & 7) << 2;
        *(uint4*)(Bs + r * NB_W + c4) = *(const uint4*)((const uint32_t*)g_ADh + r * 32 + c4);
    }
#pragma unroll
    for (int j = 0; j < 4; j++) {
        int i = t + j * 256;
        int m = i >> 4;
        int c4 = (i & 15) << 2;
        int n = n0 + m;
        if (n >= N_NODES) n = N_NODES - 1;
        float4 v = *(const float4*)(h + (size_t)n * 64 + c4);
        uint2 w = make_uint2(f2h2(v.x, v.y), f2h2(v.z, v.w));
        *(uint2*)(As + m * NA_W + (c4 >> 1)) = w;
    }
    __syncthreads();

    float c[2][4][4];
#pragma unroll
    for (int mf = 0; mf < 2; mf++)
#pragma unroll
        for (int nf = 0; nf < 4; nf++)
#pragma unroll
            for (int i = 0; i < 4; i++) c[mf][nf][i] = 0.f;

#pragma unroll
    for (int ks = 0; ks < 4; ks++) {
        int kw = ks * 8;
        uint32_t a[2][4];
#pragma unroll
        for (int mf = 0; mf < 2; mf++) {
            const uint32_t* ap = As + (mw * 32 + mf * 16 + lq) * NA_W + kw + lr;
            a[mf][0] = ap[0];
            a[mf][1] = ap[8 * NA_W];
            a[mf][2] = ap[4];
            a[mf][3] = ap[8 * NA_W + 4];
        }
        uint32_t b[4][2];
#pragma unroll
        for (int nf = 0; nf < 4; nf++) {
            const uint32_t* bp = Bs + (nw * 32 + nf * 8 + lq) * NB_W + kw + lr;
            b[nf][0] = bp[0];
            b[nf][1] = bp[4];
        }
#pragma unroll
        for (int mf = 0; mf < 2; mf++)
#pragma unroll
            for (int nf = 0; nf < 4; nf++)
                mma_f16(c[mf][nf], a[mf], b[nf]);
    }

    // store to g_PQh as fp16 (predicated on node bound)
#pragma unroll
    for (int mf = 0; mf < 2; mf++)
#pragma unroll
        for (int half = 0; half < 2; half++) {
            int r = mw * 32 + mf * 16 + half * 8 + lq;
            int n = n0 + r;
            if (n < N_NODES) {
#pragma unroll
                for (int nf = 0; nf < 4; nf++) {
                    int col = nw * 32 + nf * 8 + 2 * lr;
                    uint32_t hv = f2h2(c[mf][nf][half * 2 + 0], c[mf][nf][half * 2 + 1]);
                    *(uint32_t*)(g_PQh + (size_t)n * 128 + col) = hv;
                }
            }
        }
}

// ---------------------------------------------------------------------------
// Kernel 3: fp16 m16n8k16 edge GEMM + ldmatrix; fp16 PQ gathers (half L2 traffic).
// TILE_M=128, 2 CTAs/SM, streams evict-first, indices prefetched pre-mainloop.
// ---------------------------------------------------------------------------
#define TILE_M 128
#define NTILES (N_EDGES / TILE_M)       // 6250
#define EDGE_GRID 296                   // 148 SMs x 2 CTAs

#define EA_W 52
#define EB_W 52
#define SMEM_A_OFF 0
#define SMEM_B_OFF (TILE_M * EA_W)                 // 6656 words
#define SMEM_BIAS_OFF (SMEM_B_OFF + 64 * EB_W)     // 9984 words
#define SMEM_WORDS (SMEM_BIAS_OFF + 64)            // 10048 words = 40192 B

__global__ void __launch_bounds__(256, 2) edge_kernel(
    const float* __restrict__ e_h, const float* __restrict__ ext,
    const int* __restrict__ src, const int* __restrict__ dst,
    float* __restrict__ out)
{
    extern __shared__ uint32_t smw[];
    uint32_t* As = smw + SMEM_A_OFF;
    uint32_t* Bs = smw + SMEM_B_OFF;
    float*  bias = (float*)(smw + SMEM_BIAS_OFF);

    int t = threadIdx.x;
    int wid = t >> 5;
    int lane = t & 31;
    int mw = wid >> 1;        // 0..3 -> M rows [mw*32, +32)
    int nw = wid & 1;         // 0..1 -> N cols [nw*32, +32)
    int lq = lane >> 2;       // 0..7
    int lr = lane & 3;        // 0..3

    // stage B = g_Wch raw copy: 64 rows x 12 uint4 -> stride 52 words
#pragma unroll
    for (int j = 0; j < 4; j++) {
        int i = t + j * 256;
        int r = i >> 4;
        int s = i & 15;
        if (s < 12)
            *(uint4*)(Bs + r * EB_W + s * 4) =
                *(const uint4*)((const uint32_t*)g_Wch + r * 48 + s * 4);
    }
    if (t < 64) bias[t] = g_bias[t];

    // ldmatrix lane base addresses (bytes)
    int g8 = lane >> 3;
    int l8 = lane & 7;
    uint32_t aAddr = smem_u32(As) +
        (((mw * 32 + ((g8 & 1) ? 8 : 0) + l8) * EA_W) + ((g8 >> 1) * 4)) * 4;
    uint32_t bAddr = smem_u32(Bs) +
        (((nw * 32 + ((g8 >> 1) ? 8 : 0) + l8) * EB_W) + ((g8 & 1) * 4)) * 4;

    for (int tile = blockIdx.x; tile < NTILES; tile += EDGE_GRID) {
        int e0 = tile * TILE_M;
        __syncthreads();   // prev-iter LDS of As done (first iter: B/bias visible)

        // ---- stage A: e_h -> k 0..63 (words 0..31), streaming, cvt fp16 ----
#pragma unroll
        for (int i = t; i < 2048; i += 256) {
            int m = i >> 4;
            int c4 = (i & 15) << 2;
            float4 v = __ldcs((const float4*)(e_h + (size_t)(e0 + m) * 64 + c4));
            uint2 w = make_uint2(f2h2(v.x, v.y), f2h2(v.z, v.w));
            *(uint2*)(As + m * EA_W + (c4 >> 1)) = w;
        }
        // ---- stage A: ext -> k 64..95 (words 32..47) ----
#pragma unroll
        for (int i = t; i < 1024; i += 256) {
            int m = i >> 3;
            int c4 = (i & 7) << 2;
            float4 v = __ldcs((const float4*)(ext + (size_t)(e0 + m) * 32 + c4));
            uint2 w = make_uint2(f2h2(v.x, v.y), f2h2(v.z, v.w));
            *(uint2*)(As + m * EA_W + 32 + (c4 >> 1)) = w;
        }

        // ---- prefetch gather indices for this thread's 4 edge rows ----
        int sv[2][2], dv[2][2];
#pragma unroll
        for (int mf = 0; mf < 2; mf++)
#pragma unroll
            for (int half = 0; half < 2; half++) {
                int e = e0 + mw * 32 + mf * 16 + half * 8 + lq;
                sv[mf][half] = src[e];
                dv[mf][half] = dst[e];
            }
        __syncthreads();

        // ---- mma mainloop: 6 K-steps of 16, ldmatrix frag loads ----
        float c[2][4][4];
#pragma unroll
        for (int mf = 0; mf < 2; mf++)
#pragma unroll
            for (int nf = 0; nf < 4; nf++)
#pragma unroll
                for (int i = 0; i < 4; i++) c[mf][nf][i] = 0.f;

#pragma unroll
        for (int ks = 0; ks < 6; ks++) {
            uint32_t kofs = ks * 32;
            uint32_t a[2][4];
            ldsm_x4(a[0][0], a[0][1], a[0][2], a[0][3], aAddr + kofs);
            ldsm_x4(a[1][0], a[1][1], a[1][2], a[1][3], aAddr + 16 * EA_W * 4 + kofs);
            uint32_t b[4][2];
            ldsm_x4(b[0][0], b[0][1], b[1][0], b[1][1], bAddr + kofs);
            ldsm_x4(b[2][0], b[2][1], b[3][0], b[3][1], bAddr + 16 * EB_W * 4 + kofs);
#pragma unroll
            for (int mf = 0; mf < 2; mf++)
#pragma unroll
                for (int nf = 0; nf < 4; nf++)
                    mma_f16(c[mf][nf], a[mf], b[nf]);
        }

        // ---- epilogue: +P[src] +Q[dst] (fp16 gathers) +bias, ReLU, store ----
#pragma unroll
        for (int mf = 0; mf < 2; mf++) {
#pragma unroll
            for (int half = 0; half < 2; half++) {
                int r = mw * 32 + mf * 16 + half * 8 + lq;
                int e = e0 + r;
                const __half* P = g_PQh + (size_t)sv[mf][half] * 128;
                const __half* Q = g_PQh + (size_t)dv[mf][half] * 128 + 64;
#pragma unroll
                for (int nf = 0; nf < 4; nf++) {
                    int col = nw * 32 + nf * 8 + 2 * lr;
                    __half2 ph = __ldg((const __half2*)(P + col));
                    __half2 qh = __ldg((const __half2*)(Q + col));
                    float2 p = __half22float2(ph);
                    float2 q = __half22float2(qh);
                    float2 bvv = *(const float2*)(bias + col);
                    float cx = c[mf][nf][half * 2 + 0];
                    float cy = c[mf][nf][half * 2 + 1];
                    float2 rv;
                    rv.x = fmaxf(cx + p.x + q.x + bvv.x, 0.f);
                    rv.y = fmaxf(cy + p.y + q.y + bvv.y, 0.f);
                    stg_cs(out + (size_t)e * 64 + col, rv);
                }
            }
        }
    }
}

// ---------------------------------------------------------------------------
extern "C" void kernel_launch(void* const* d_in, const int* in_sizes, int n_in,
                              void* d_out, int out_size) {
    const float* h   = (const float*)d_in[0];
    const float* e_h = (const float*)d_in[1];
    const float* ext = (const float*)d_in[2];
    const float* W1  = (const float*)d_in[3];
    const float* b1  = (const float*)d_in[4];
    const float* W2  = (const float*)d_in[5];
    const float* b2  = (const float*)d_in[6];
    const int*   src = (const int*)d_in[7];
    const int*   dst = (const int*)d_in[8];
    float* out = (float*)d_out;

    static bool attr_set = false;
    if (!attr_set) {
        cudaFuncSetAttribute(edge_kernel, cudaFuncAttributeMaxDynamicSharedMemorySize,
                             SMEM_WORDS * 4);
        cudaFuncSetAttribute(node_kernel, cudaFuncAttributeMaxDynamicSharedMemorySize,
                             NSM_WORDS * 4);
        attr_set = true;
    }

    prep_kernel<<<48, 256>>>(W1, b1, W2, b2);
    node_kernel<<<(N_NODES + 63) / 64, 256, NSM_WORDS * 4>>>(h);
    edge_kernel<<<EDGE_GRID, 256, SMEM_WORDS * 4>>>(e_h, ext, src, dst, out);
}